// round 1
// baseline (speedup 1.0000x reference)
#include <cuda_runtime.h>
#include <cuda_bf16.h>

// Scales: S={56,28,14,7}, C={64,128,256,512}, HW={3136,784,196,49}
// HWC scratch offsets (floats): 0, 200704, 301056, 351232; total 376320 floats.
#define HWC_TOTAL 376320
#define NPTS_MAX  131072

__device__ float  g_hwc[HWC_TOTAL];
__device__ float2 g_hw[NPTS_MAX];

// Pre-pass: (a) transpose batch-b CHW slices -> HWC scratch, (b) per-point (h,w).
__global__ void prep_kernel(const float* __restrict__ f0, const float* __restrict__ f1,
                            const float* __restrict__ f2, const float* __restrict__ f3,
                            const float* __restrict__ pts, const int* __restrict__ bptr,
                            int N)
{
    int tid = blockIdx.x * blockDim.x + threadIdx.x;
    if (tid < HWC_TOTAL) {
        int b = bptr ? *bptr : 3;
        const float* src; int e, clog2, HW;
        if (tid < 200704)      { src = f0; e = tid;          clog2 = 6; HW = 3136; }
        else if (tid < 301056) { src = f1; e = tid - 200704; clog2 = 7; HW = 784;  }
        else if (tid < 351232) { src = f2; e = tid - 301056; clog2 = 8; HW = 196;  }
        else                   { src = f3; e = tid - 351232; clog2 = 9; HW = 49;   }
        int C = 1 << clog2;
        int c = e & (C - 1);       // channel (fastest in dst)
        int p = e >> clog2;        // pixel index
        // dst[off + p*C + c] == g_hwc[tid]; src[b*C*HW + c*HW + p]
        g_hwc[tid] = src[(size_t)b * C * HW + (size_t)c * HW + p];
    } else {
        int n = tid - HWC_TOTAL;
        if (n < N) {
            float p0 = pts[3 * n + 0];
            float p1 = pts[3 * n + 1];
            float p2 = pts[3 * n + 2];
            float h = 248.0f * (p1 / p2) + 111.5f;
            float w = 248.0f * (p0 / (-p2)) + 111.5f;
            h = fminf(fmaxf(h, 0.0f), 223.0f);
            w = fminf(fmaxf(w, 0.0f), 223.0f);
            g_hw[n] = make_float2(h, w);
        }
    }
}

// Main kernel: one thread per (point, float4-chunk). 960 floats/point = 240 float4.
// chunk [0,16): scale0; [16,48): scale1; [48,112): scale2; [112,240): scale3.
__global__ void gather_kernel(float4* __restrict__ out, int N)
{
    int gid = blockIdx.x * blockDim.x + threadIdx.x;
    unsigned n = (unsigned)gid / 240u;
    if (n >= (unsigned)N) return;
    int chunk = gid - (int)n * 240;

    float2 hw = g_hw[n];

    int S, C, base, c4; float inv;
    if (chunk < 16)       { S = 56; C = 64;  base = 0;      c4 = chunk;       inv = 0.25f;    }
    else if (chunk < 48)  { S = 28; C = 128; base = 200704; c4 = chunk - 16;  inv = 0.125f;   }
    else if (chunk < 112) { S = 14; C = 256; base = 301056; c4 = chunk - 48;  inv = 0.0625f;  }
    else                  { S = 7;  C = 512; base = 351232; c4 = chunk - 112; inv = 0.03125f; }

    float x = hw.x * inv;   // matches h / (224/S): divisor is an exact power of two
    float y = hw.y * inv;
    int x1 = (int)floorf(x);
    int y1 = (int)floorf(y);
    int x2 = min((int)ceilf(x), S - 1);
    int y2 = min((int)ceilf(y), S - 1);
    // xl==x1, yl==y1 (x,y >= 0), so only w11 = (x2-x1)*(y2-y1) in {0,1} survives.
    int wgt = (x2 - x1) * (y2 - y1);

    float4 v = make_float4(0.0f, 0.0f, 0.0f, 0.0f);
    if (wgt != 0) {
        const float4* src =
            (const float4*)&g_hwc[base + (x1 * S + y1) * C];
        v = src[c4];
    }
    out[gid] = v;
}

extern "C" void kernel_launch(void* const* d_in, const int* in_sizes, int n_in,
                              void* d_out, int out_size)
{
    const float* f0  = (const float*)d_in[0];
    const float* f1  = (const float*)d_in[1];
    const float* f2  = (const float*)d_in[2];
    const float* f3  = (const float*)d_in[3];
    const float* pts = (const float*)d_in[4];
    const int*   bp  = (n_in >= 6) ? (const int*)d_in[5] : nullptr;

    int N = in_sizes[4] / 3;
    if (N > NPTS_MAX) N = NPTS_MAX;

    {
        int total = HWC_TOTAL + N;
        int threads = 256;
        int blocks = (total + threads - 1) / threads;
        prep_kernel<<<blocks, threads>>>(f0, f1, f2, f3, pts, bp, N);
    }
    {
        long long total = (long long)N * 240;
        int threads = 256;
        int blocks = (int)((total + threads - 1) / threads);
        gather_kernel<<<blocks, threads>>>((float4*)d_out, N);
    }
}